// round 8
// baseline (speedup 1.0000x reference)
#include <cuda_runtime.h>
#include <cstdint>

// Problem constants
#define B_   64
#define L_   32
#define D_   64
#define V_   100000
#define TIN  8
#define THID 128
#define R_   2048
#define LOSS_T 29
#define NT_TILES 782           // ceil(100000/128)
#define TPC 42                 // tiles per venue-chunk
#define NCH 19                 // 19*42 = 798 >= 782
#define EPS_RANK 2.0e-2f

// ---------------- scratch ----------------
__device__ float g_time_emb[R_ * D_];
__device__ float g_x[R_ * D_];
__device__ float g_seq[R_ * D_];      // exact fp32
__device__ float g_seqR[R_ * D_];     // tf32-rounded (rna)
__device__ float g_lt[R_];
__device__ float g_mom[R_ * 4];       // loss rows: s1 ; topk rows: gt-count
__device__ float g_vtP[NT_TILES * 8192];  // venue table, tf32, mma-fragment order

// ---------------- exp helpers ----------------
// accurate (deg-4) — used only in k_final for exp(lt)
__device__ __forceinline__ float fexp(float x) {
    float t = x * 1.4426950408889634f;
    float z = t + 12582912.0f;
    int   n = __float_as_int(z) - 0x4B400000;
    float r = t - (z - 12582912.0f);
    float p = fmaf(9.6181291e-3f, r, 5.5504109e-2f);
    p = fmaf(p, r, 2.4022651e-1f);
    p = fmaf(p, r, 6.9314718e-1f);
    p = fmaf(p, r, 1.0f);
    return __int_as_float(__float_as_int(p) + (n << 23));
}
// Schraudolph (3 inst) — s1 accumulation; rel err ~4%, pt ~1e-5 -> loss err ~1e-7
__device__ __forceinline__ float schr(float x) {
    return __int_as_float(__float2int_rz(fmaf(x, 12102203.0f, 1064866805.0f)));
}
__device__ __forceinline__ float tf32r(float x) {
    uint32_t u;
    asm("cvt.rna.tf32.f32 %0, %1;" : "=r"(u) : "f"(x));
    return __uint_as_float(u);
}

// ---------------- K0: prepack venue table into mma B-fragment order ----------------
// idx bits: j(1) | lane(5) | ks(3) | nb(4) | tile
// B frag (col-major 8x8): b_j at k = ks*8 + lane%4 + j*4, n = nb*8 + lane/4
__global__ void k_prepack(const float* __restrict__ vt) {
    int idx = blockIdx.x * 256 + threadIdx.x;     // exactly NT_TILES*8192
    int j  = idx & 1;
    int l  = (idx >> 1) & 31;
    int ks = (idx >> 6) & 7;
    int nb = (idx >> 9) & 15;
    int T  = idx >> 13;
    int v = T * 128 + nb * 8 + (l >> 2);
    int k = ks * 8 + (l & 3) + j * 4;
    g_vtP[idx] = (v < V_) ? tf32r(vt[v * 64 + k]) : 0.f;
}

// ---------------- K1: time MLP + venue gather ----------------
__global__ void k_embed(const float* __restrict__ time, const int* __restrict__ venue,
                        const float* __restrict__ vt,
                        const float* __restrict__ w1, const float* __restrict__ b1,
                        const float* __restrict__ w2, const float* __restrict__ b2) {
    int row = blockIdx.x;
    int tid = threadIdx.x;
    __shared__ float ts[TIN];
    __shared__ float hid[THID];
    if (tid < TIN) ts[tid] = time[row * TIN + tid];
    __syncthreads();
    float a = b1[tid];
#pragma unroll
    for (int k = 0; k < TIN; k++) a = fmaf(ts[k], w1[k * THID + tid], a);
    hid[tid] = fmaxf(a, 0.f);
    __syncthreads();
    if (tid < D_) {
        float te = b2[tid];
#pragma unroll 16
        for (int j = 0; j < THID; j++) te = fmaf(hid[j], w2[j * D_ + tid], te);
        g_time_emb[row * D_ + tid] = te;
        int vv = venue[row];
        g_x[row * D_ + tid] = vt[vv * D_ + tid] + te;
    }
}

// ---------------- K2: RNN ----------------
__global__ void k_rnn(const int* __restrict__ user, const float* __restrict__ user_table,
                      const float* __restrict__ Wih, const float* __restrict__ Whh,
                      const float* __restrict__ bih, const float* __restrict__ bhh) {
    int b = blockIdx.x;
    int tid = threadIdx.x;
    __shared__ float WihT[D_ * D_];
    __shared__ float WhhT[D_ * D_];
    __shared__ float h[D_];
    __shared__ float xs[D_];
    for (int i = 0; i < D_; i++) {
        WihT[i * D_ + tid] = Wih[tid * D_ + i];
        WhhT[i * D_ + tid] = Whh[tid * D_ + i];
    }
    h[tid] = user_table[user[b] * D_ + tid];
    float bias = bih[tid] + bhh[tid];
    __syncthreads();
    for (int t = 0; t < L_; t++) {
        int r = b * L_ + t;
        float sv = h[tid] - g_time_emb[r * D_ + tid];
        g_seq[r * D_ + tid] = sv;
        g_seqR[r * D_ + tid] = tf32r(sv);
        xs[tid] = g_x[r * D_ + tid];
        __syncthreads();
        float a = bias;
#pragma unroll 16
        for (int k = 0; k < D_; k++)
            a = fmaf(xs[k], WihT[k * D_ + tid], fmaf(h[k], WhhT[k * D_ + tid], a));
        __syncthreads();
        h[tid] = tanhf(a);
        __syncthreads();
    }
}

// ---------------- K3: target logits + zero stats ----------------
__global__ void k_target(const int* __restrict__ venue, const float* __restrict__ vt) {
    int r = blockIdx.x;
    int tid = threadIdx.x;       // 64
    if (tid < 4) g_mom[r * 4 + tid] = 0.f;
    int tgt = venue[r];
    float v = g_seq[r * D_ + tid] * vt[tgt * D_ + tid];
#pragma unroll
    for (int o = 16; o; o >>= 1) v += __shfl_down_sync(0xffffffffu, v, o);
    __shared__ float p2[2];
    if ((tid & 31) == 0) p2[tid >> 5] = v;
    __syncthreads();
    if (tid == 0) g_lt[r] = p2[0] + p2[1];
}

// ---------------- K4: tensor-core main pass (mma.sync tf32) ----------------
#define DYN_SMEM (32768 + 2 * 32768)

__global__ void __launch_bounds__(256, 2)
k_main(const float* __restrict__ vt, const int* __restrict__ venue) {
    extern __shared__ float sm[];
    float* smA = sm;               // A fragments: 8192 floats
    float* smB = sm + 8192;        // B double buffer: 2 x 8192 floats

    const int tid   = threadIdx.x;
    const int lane  = tid & 31, wid = tid >> 5;
    const int warpM = wid >> 2, warpN = wid & 3;
    const int g = lane >> 2, tig = lane & 3;
    const int row0 = blockIdx.y * 128;
    const int t0 = blockIdx.x * TPC;
    const int nt = min(NT_TILES - t0, TPC);

    // ---- pack A fragments: A_frag[mblk][ks][lane][4] ----
    // a_j: row = mblk*16 + lane/4 + (j&1)*8 ; k = ks*8 + lane%4 + (j>>1)*4
#pragma unroll
    for (int i = 0; i < 32; i++) {
        int o = i * 256 + tid;
        int j = o & 3, l = (o >> 2) & 31, ks = (o >> 7) & 7, mb = o >> 10;
        int row = row0 + mb * 16 + (l >> 2) + (j & 1) * 8;
        int k = ks * 8 + (l & 3) + (j >> 1) * 4;
        smA[o] = g_seqR[row * 64 + k];
    }

    // ---- topk row metadata: only mf in {1,3}, hi half, g>=5 are topk rows ----
    int r1 = row0 + warpM * 64 + 16 + 8 + g;   // mf=1 hi
    int r3 = row0 + warpM * 64 + 48 + 8 + g;   // mf=3 hi
    const float thr1 = g_lt[r1], thr3 = g_lt[r3];
    const int   tgt1 = venue[r1], tgt3 = venue[r3];
    const bool topg = (g >= 5);

    float stat[4][2];
#pragma unroll
    for (int a = 0; a < 4; a++) { stat[a][0] = 0.f; stat[a][1] = 0.f; }

    // ---- prefetch tile 0 (contiguous 32KB) ----
    {
        const char* src = (const char*)(g_vtP + (size_t)t0 * 8192);
        uint32_t d0 = (uint32_t)__cvta_generic_to_shared(smB);
#pragma unroll
        for (int i = 0; i < 8; i++)
            asm volatile("cp.async.cg.shared.global [%0], [%1], 16;"
                         :: "r"(d0 + tid * 16 + i * 4096),
                            "l"(src + tid * 16 + i * 4096) : "memory");
        asm volatile("cp.async.commit_group;" ::: "memory");
    }

    for (int t = 0; t < nt; t++) {
        if (t + 1 < nt) {
            const char* src = (const char*)(g_vtP + (size_t)(t0 + t + 1) * 8192);
            uint32_t d0 = (uint32_t)__cvta_generic_to_shared(smB + ((t + 1) & 1) * 8192);
#pragma unroll
            for (int i = 0; i < 8; i++)
                asm volatile("cp.async.cg.shared.global [%0], [%1], 16;"
                             :: "r"(d0 + tid * 16 + i * 4096),
                                "l"(src + tid * 16 + i * 4096) : "memory");
            asm volatile("cp.async.commit_group;" ::: "memory");
            asm volatile("cp.async.wait_group 1;" ::: "memory");
        } else {
            asm volatile("cp.async.wait_group 0;" ::: "memory");
        }
        __syncthreads();

        const float* bb = smB + (t & 1) * 8192;

        float acc[4][4][4];
#pragma unroll
        for (int a = 0; a < 4; a++)
#pragma unroll
            for (int b = 0; b < 4; b++) {
                acc[a][b][0] = 0.f; acc[a][b][1] = 0.f;
                acc[a][b][2] = 0.f; acc[a][b][3] = 0.f;
            }

#pragma unroll
        for (int ks = 0; ks < 8; ks++) {
            uint4 av[4];
#pragma unroll
            for (int mf = 0; mf < 4; mf++)
                av[mf] = *(const uint4*)(smA + (((warpM * 4 + mf) * 8 + ks) * 128 + lane * 4));
#pragma unroll
            for (int nf = 0; nf < 4; nf++) {
                uint2 bv = *(const uint2*)(bb + (((warpN * 4 + nf) * 8 + ks) * 64 + lane * 2));
#pragma unroll
                for (int mf = 0; mf < 4; mf++) {
                    asm volatile(
                        "mma.sync.aligned.m16n8k8.row.col.f32.tf32.tf32.f32 "
                        "{%0,%1,%2,%3}, {%4,%5,%6,%7}, {%8,%9}, {%0,%1,%2,%3};"
                        : "+f"(acc[mf][nf][0]), "+f"(acc[mf][nf][1]),
                          "+f"(acc[mf][nf][2]), "+f"(acc[mf][nf][3])
                        : "r"(av[mf].x), "r"(av[mf].y), "r"(av[mf].z), "r"(av[mf].w),
                          "r"(bv.x), "r"(bv.y));
                }
            }
        }

        // ---- epilogue on register fragments ----
        int vbase = (t0 + t) * 128 + warpN * 32;
#pragma unroll
        for (int mf = 0; mf < 4; mf++) {
            bool hiTop = ((mf & 1) == 1) && topg;
#pragma unroll
            for (int nf = 0; nf < 4; nf++) {
                // lo row (t <= 23): always loss
                stat[mf][0] += schr(acc[mf][nf][0]) + schr(acc[mf][nf][1]);
                if (!hiTop) {
                    stat[mf][1] += schr(acc[mf][nf][2]) + schr(acc[mf][nf][3]);
                } else {
                    float thr = (mf == 1) ? thr1 : thr3;
                    int   tgt = (mf == 1) ? tgt1 : tgt3;
                    int   rrow = (mf == 1) ? r1 : r3;
                    int v0 = vbase + nf * 8 + tig * 2;
#pragma unroll
                    for (int q = 0; q < 2; q++) {
                        int v = v0 + q;
                        float l = acc[mf][nf][2 + q];
                        float dd = l - thr;
                        if (v < V_ && v != tgt && dd > -EPS_RANK) {
                            if (dd > EPS_RANK) stat[mf][1] += 1.f;
                            else {
                                const float* sr = g_seq + (size_t)rrow * 64;
                                const float* vr = vt + (size_t)v * 64;
                                float ex = 0.f;
#pragma unroll 16
                                for (int k = 0; k < 64; k++) ex = fmaf(sr[k], vr[k], ex);
                                if (ex > thr) stat[mf][1] += 1.f;
                            }
                        }
                    }
                }
            }
        }
        __syncthreads();   // protect smB buffer reuse
    }

    // ---- reduce 4 lanes sharing each row, then atomic ----
#pragma unroll
    for (int mf = 0; mf < 4; mf++)
#pragma unroll
        for (int h = 0; h < 2; h++) {
            float v = stat[mf][h];
            v += __shfl_down_sync(0xffffffffu, v, 2);
            v += __shfl_down_sync(0xffffffffu, v, 1);
            if (tig == 0) {
                int row = row0 + warpM * 64 + mf * 16 + h * 8 + g;
                atomicAdd(&g_mom[row * 4], v);
            }
        }
}

// ---------------- K5: finalize loss + counts ----------------
__global__ void k_final(float* __restrict__ out) {
    int tid = threadIdx.x;   // 256
    float loss = 0.f, c1 = 0.f, c5 = 0.f, c10 = 0.f, c20 = 0.f;
    const float logS = logf((float)V_ + 1.0f);
    for (int r = tid; r < R_; r += 256) {
        int t = r & 31;
        if (t < LOSS_T) {
            float s1 = g_mom[r * 4 + 0];
            float pt = fexp(g_lt[r]) / s1;
            loss += (logS - pt);
        } else {
            int rank = (int)(g_mom[r * 4 + 0] + 0.5f);
            c1  += (rank < 1);
            c5  += (rank < 5);
            c10 += (rank < 10);
            c20 += (rank < 20);
        }
    }
    __shared__ float sm[256];
    float vals[5] = {loss, c1, c5, c10, c20};
    float tot[5];
#pragma unroll
    for (int q = 0; q < 5; q++) {
        sm[tid] = vals[q];
        __syncthreads();
        for (int s = 128; s; s >>= 1) {
            if (tid < s) sm[tid] += sm[tid + s];
            __syncthreads();
        }
        tot[q] = sm[0];
        __syncthreads();
    }
    if (tid == 0) {
        out[0] = tot[0] / (float)(B_ * LOSS_T);
        out[1] = tot[1];
        out[2] = tot[2];
        out[3] = tot[3];
        out[4] = tot[4];
        out[5] = (float)(B_ * 3);
    }
}

// ---------------- launch ----------------
extern "C" void kernel_launch(void* const* d_in, const int* in_sizes, int n_in,
                              void* d_out, int out_size) {
    const int*   user   = (const int*)  d_in[0];
    const int*   venue  = (const int*)  d_in[1];
    const float* time   = (const float*)d_in[2];
    const float* vt     = (const float*)d_in[3];
    const float* ut     = (const float*)d_in[4];
    const float* w1     = (const float*)d_in[5];
    const float* b1     = (const float*)d_in[6];
    const float* w2     = (const float*)d_in[7];
    const float* b2     = (const float*)d_in[8];
    const float* Wih    = (const float*)d_in[9];
    const float* Whh    = (const float*)d_in[10];
    const float* bih    = (const float*)d_in[11];
    const float* bhh    = (const float*)d_in[12];
    float* out = (float*)d_out;

    cudaFuncSetAttribute(k_main, cudaFuncAttributeMaxDynamicSharedMemorySize, DYN_SMEM);

    k_prepack<<<NT_TILES * 32, 256>>>(vt);
    k_embed<<<R_, THID>>>(time, venue, vt, w1, b1, w2, b2);
    k_rnn<<<B_, D_>>>(user, ut, Wih, Whh, bih, bhh);
    k_target<<<R_, D_>>>(venue, vt);
    dim3 g4(NCH, 16);
    k_main<<<g4, 256, DYN_SMEM>>>(vt, venue);
    k_final<<<1, 256>>>(out);
}

// round 9
// speedup vs baseline: 1.3012x; 1.3012x over previous
#include <cuda_runtime.h>
#include <cstdint>

// Problem constants
#define B_   64
#define L_   32
#define D_   64
#define V_   100000
#define TIN  8
#define THID 128
#define R_   2048
#define LOSS_T 29

// ---------------- scratch ----------------
__device__ float g_time_emb[R_ * D_];
__device__ float g_x[R_ * D_];
__device__ float g_seq[R_ * D_];
__device__ float g_lt[R_];
__device__ float g_mom[R_ * 4];      // loss rows: s1 ; topk rows: gt-count
__device__ float g_vtT[D_ * V_];     // venue table transposed [k][v]

// ---------------- exp helpers ----------------
// accurate (deg-6) — used only in k_final for exp(lt)
__device__ __forceinline__ float fexp(float x) {
    float t = x * 1.4426950408889634f;
    float z = t + 12582912.0f;
    int   n = __float_as_int(z) - 0x4B400000;
    float r = t - (z - 12582912.0f);
    float p = fmaf(1.5403530e-4f, r, 1.3333558e-3f);
    p = fmaf(p, r, 9.6181291e-3f);
    p = fmaf(p, r, 5.5504109e-2f);
    p = fmaf(p, r, 2.4022651e-1f);
    p = fmaf(p, r, 6.9314718e-1f);
    p = fmaf(p, r, 1.0f);
    return __int_as_float(__float_as_int(p) + (n << 23));
}
// Schraudolph (2 inst) — s1 accumulation; |rel err| <= ~4%, harmless for pt ~ 1e-5..1e-2
__device__ __forceinline__ float schr(float x) {
    return __int_as_float(__float2int_rz(fmaf(x, 12102203.0f, 1064866805.0f)));
}

__device__ __forceinline__ void ffma2(unsigned long long& d,
                                      unsigned long long a,
                                      unsigned long long b) {
    asm("fma.rn.f32x2 %0, %1, %2, %0;" : "+l"(d) : "l"(a), "l"(b));
}
__device__ __forceinline__ unsigned smem_u32(const void* p) {
    return (unsigned)__cvta_generic_to_shared(p);
}

// ---------------- K0: transpose venue_table -> g_vtT [k][v] ----------------
__global__ void k_transpose(const float* __restrict__ vt) {
    __shared__ float s[D_ * 33];
    const int tx = threadIdx.x, ty = threadIdx.y;
    const int tid = ty * 32 + tx;
    const int v0 = blockIdx.x * 32;
#pragma unroll
    for (int i = 0; i < 8; i++) {
        int off = tid + i * 256;
        int vl = off >> 6, k = off & 63;
        s[k * 33 + vl] = vt[v0 * 64 + off];
    }
    __syncthreads();
#pragma unroll
    for (int i = 0; i < 8; i++) {
        int k = i * 8 + ty;
        g_vtT[(size_t)k * V_ + v0 + tx] = s[k * 33 + tx];
    }
}

// ---------------- K1: time MLP + venue gather ----------------
__global__ void k_embed(const float* __restrict__ time, const int* __restrict__ venue,
                        const float* __restrict__ vt,
                        const float* __restrict__ w1, const float* __restrict__ b1,
                        const float* __restrict__ w2, const float* __restrict__ b2) {
    int row = blockIdx.x;
    int tid = threadIdx.x;
    __shared__ float ts[TIN];
    __shared__ float hid[THID];
    if (tid < TIN) ts[tid] = time[row * TIN + tid];
    __syncthreads();
    float a = b1[tid];
#pragma unroll
    for (int k = 0; k < TIN; k++) a = fmaf(ts[k], w1[k * THID + tid], a);
    hid[tid] = fmaxf(a, 0.f);
    __syncthreads();
    if (tid < D_) {
        float te = b2[tid];
#pragma unroll 16
        for (int j = 0; j < THID; j++) te = fmaf(hid[j], w2[j * D_ + tid], te);
        g_time_emb[row * D_ + tid] = te;
        int vv = venue[row];
        g_x[row * D_ + tid] = vt[vv * D_ + tid] + te;
    }
}

// ---------------- K2: RNN ----------------
__global__ void k_rnn(const int* __restrict__ user, const float* __restrict__ user_table,
                      const float* __restrict__ Wih, const float* __restrict__ Whh,
                      const float* __restrict__ bih, const float* __restrict__ bhh) {
    int b = blockIdx.x;
    int tid = threadIdx.x;
    __shared__ float WihT[D_ * D_];
    __shared__ float WhhT[D_ * D_];
    __shared__ float h[D_];
    __shared__ float xs[D_];
    for (int i = 0; i < D_; i++) {
        WihT[i * D_ + tid] = Wih[tid * D_ + i];
        WhhT[i * D_ + tid] = Whh[tid * D_ + i];
    }
    h[tid] = user_table[user[b] * D_ + tid];
    float bias = bih[tid] + bhh[tid];
    __syncthreads();
    for (int t = 0; t < L_; t++) {
        int r = b * L_ + t;
        g_seq[r * D_ + tid] = h[tid] - g_time_emb[r * D_ + tid];
        xs[tid] = g_x[r * D_ + tid];
        __syncthreads();
        float a = bias;
#pragma unroll 16
        for (int k = 0; k < D_; k++)
            a = fmaf(xs[k], WihT[k * D_ + tid], fmaf(h[k], WhhT[k * D_ + tid], a));
        __syncthreads();
        h[tid] = tanhf(a);
        __syncthreads();
    }
}

// ---------------- K3: target logits + zero stats ----------------
__global__ void k_target(const int* __restrict__ venue, const float* __restrict__ vt) {
    int r = blockIdx.x;
    int tid = threadIdx.x;       // 64
    if (tid < 4) g_mom[r * 4 + tid] = 0.f;
    int tgt = venue[r];
    float v = g_seq[r * D_ + tid] * vt[tgt * D_ + tid];
#pragma unroll
    for (int o = 16; o; o >>= 1) v += __shfl_down_sync(0xffffffffu, v, o);
    __shared__ float p2[2];
    if ((tid & 31) == 0) p2[tid >> 5] = v;
    __syncthreads();
    if (tid == 0) g_lt[r] = p2[0] + p2[1];
}

// ---------------- K4: main pass — 16 rows/warp, f32x2, Schraudolph ----------------
#define VT 128
#define VCHUNK 4352            // 34 tiles of 128
#define NVCH 23                // 23*4352 >= 100000
#define DYN_SMEM 65536         // venT 32KB + seqDup 32KB

__global__ void __launch_bounds__(128, 3)
k_main(const int* __restrict__ venue) {
    extern __shared__ __align__(16) char dsm[];
    float*  venT   = (float*)dsm;                 // [k][128v]   32 KB
    float2* seqDup = (float2*)(dsm + 32768);      // [k][64r dup] 32 KB

    const int tx  = threadIdx.x;      // 0..31 -> 4 venues each
    const int ty  = threadIdx.y;      // 0..3  -> 16 rows each
    const int tid = ty * 32 + tx;
    const int row0 = blockIdx.y * 64;             // 64 rows per CTA (2 batches)
    const int vstart = blockIdx.x * VCHUNK;
    const int vend   = min(V_, vstart + VCHUNK);

    // load seq tile (k-major, duplicated pairs for f32x2): 64 rows x 64 k
    for (int e = tid; e < D_ * 64; e += 128) {
        int r = e & 63, k = e >> 6;
        float s = g_seq[(row0 + r) * D_ + k];
        seqDup[k * 64 + r] = make_float2(s, s);
    }
    // per-row metadata (16 rows per thread-row-group)
    float thr[16]; int tgtv[16]; float stat[16];
#pragma unroll
    for (int i = 0; i < 16; i++) {
        int r = row0 + ty * 16 + i;
        thr[i] = g_lt[r]; tgtv[i] = venue[r]; stat[i] = 0.f;
    }
    __syncthreads();

    const ulonglong2* venp = reinterpret_cast<const ulonglong2*>(venT);
    const ulonglong2* seqp = reinterpret_cast<const ulonglong2*>(seqDup);

    for (int vbase = vstart; vbase < vend; vbase += VT) {
        // coalesced async tile load from transposed table
#pragma unroll
        for (int i = 0; i < 16; i++) {
            int f = tid + i * 128;          // 0..2047 float4 slots
            int k = f >> 5, vl4 = f & 31;
            int v = vbase + vl4 * 4;
            float* dst = venT + k * VT + vl4 * 4;
            if (v < V_) {
                const float* src = g_vtT + (size_t)k * V_ + v;
                asm volatile("cp.async.cg.shared.global [%0], [%1], 16;"
                             :: "r"(smem_u32(dst)), "l"(src) : "memory");
            } else {
                *reinterpret_cast<float4*>(dst) = make_float4(0.f, 0.f, 0.f, 0.f);
            }
        }
        asm volatile("cp.async.commit_group;" ::: "memory");
        asm volatile("cp.async.wait_group 0;" ::: "memory");
        __syncthreads();

        unsigned long long acc[16][2];
#pragma unroll
        for (int i = 0; i < 16; i++) { acc[i][0] = 0ull; acc[i][1] = 0ull; }

#pragma unroll 8
        for (int k = 0; k < D_; k++) {
            ulonglong2 vv = venp[k * 32 + tx];            // venues 4tx..4tx+3
#pragma unroll
            for (int j = 0; j < 8; j++) {
                ulonglong2 s = seqp[k * 32 + ty * 8 + j]; // rows 16ty+2j, +2j+1 (dup)
                ffma2(acc[2*j  ][0], s.x, vv.x); ffma2(acc[2*j  ][1], s.x, vv.y);
                ffma2(acc[2*j+1][0], s.y, vv.x); ffma2(acc[2*j+1][1], s.y, vv.y);
            }
        }

        int v0 = vbase + 4 * tx;
#pragma unroll
        for (int i = 0; i < 16; i++) {
            float l[4];
            l[0] = __uint_as_float((unsigned)(acc[i][0]));
            l[1] = __uint_as_float((unsigned)(acc[i][0] >> 32));
            l[2] = __uint_as_float((unsigned)(acc[i][1]));
            l[3] = __uint_as_float((unsigned)(acc[i][1] >> 32));
            if (((ty * 16 + i) & 31) >= LOSS_T) {          // topk row: exact rank count
#pragma unroll
                for (int j = 0; j < 4; j++)
                    if (v0 + j < V_ && v0 + j != tgtv[i] && l[j] > thr[i]) stat[i] += 1.f;
            } else {                                       // loss row: cheap s1
                stat[i] += (schr(l[0]) + schr(l[1])) + (schr(l[2]) + schr(l[3]));
            }
        }
        __syncthreads();
    }

    // warp reduce (32 lanes of a warp share the same 16 rows)
#pragma unroll
    for (int i = 0; i < 16; i++) {
        float s = stat[i];
#pragma unroll
        for (int o = 16; o; o >>= 1) s += __shfl_down_sync(0xffffffffu, s, o);
        if (tx == 0) atomicAdd(&g_mom[(row0 + ty * 16 + i) * 4], s);
    }
}

// ---------------- K5: finalize loss + counts ----------------
__global__ void k_final(float* __restrict__ out) {
    int tid = threadIdx.x;   // 256
    float loss = 0.f, c1 = 0.f, c5 = 0.f, c10 = 0.f, c20 = 0.f;
    const float logS = logf((float)V_ + 1.0f);
    for (int r = tid; r < R_; r += 256) {
        int t = r & 31;
        if (t < LOSS_T) {
            float s1 = g_mom[r * 4 + 0];
            float pt = fexp(g_lt[r]) / s1;
            loss += (logS - pt);
        } else {
            int rank = (int)(g_mom[r * 4 + 0] + 0.5f);
            c1  += (rank < 1);
            c5  += (rank < 5);
            c10 += (rank < 10);
            c20 += (rank < 20);
        }
    }
    __shared__ float sm[256];
    float vals[5] = {loss, c1, c5, c10, c20};
    float tot[5];
#pragma unroll
    for (int q = 0; q < 5; q++) {
        sm[tid] = vals[q];
        __syncthreads();
        for (int s = 128; s; s >>= 1) {
            if (tid < s) sm[tid] += sm[tid + s];
            __syncthreads();
        }
        tot[q] = sm[0];
        __syncthreads();
    }
    if (tid == 0) {
        out[0] = tot[0] / (float)(B_ * LOSS_T);
        out[1] = tot[1];
        out[2] = tot[2];
        out[3] = tot[3];
        out[4] = tot[4];
        out[5] = (float)(B_ * 3);
    }
}

// ---------------- launch ----------------
extern "C" void kernel_launch(void* const* d_in, const int* in_sizes, int n_in,
                              void* d_out, int out_size) {
    const int*   user   = (const int*)  d_in[0];
    const int*   venue  = (const int*)  d_in[1];
    const float* time   = (const float*)d_in[2];
    const float* vt     = (const float*)d_in[3];
    const float* ut     = (const float*)d_in[4];
    const float* w1     = (const float*)d_in[5];
    const float* b1     = (const float*)d_in[6];
    const float* w2     = (const float*)d_in[7];
    const float* b2     = (const float*)d_in[8];
    const float* Wih    = (const float*)d_in[9];
    const float* Whh    = (const float*)d_in[10];
    const float* bih    = (const float*)d_in[11];
    const float* bhh    = (const float*)d_in[12];
    float* out = (float*)d_out;

    cudaFuncSetAttribute(k_main, cudaFuncAttributeMaxDynamicSharedMemorySize, DYN_SMEM);

    dim3 bt(32, 8);
    k_transpose<<<V_ / 32, bt>>>(vt);
    k_embed<<<R_, THID>>>(time, venue, vt, w1, b1, w2, b2);
    k_rnn<<<B_, D_>>>(user, ut, Wih, Whh, bih, bhh);
    k_target<<<R_, D_>>>(venue, vt);
    dim3 g4(NVCH, R_ / 64), b4(32, 4);
    k_main<<<g4, b4, DYN_SMEM>>>(venue);
    k_final<<<1, 256>>>(out);
}